// round 17
// baseline (speedup 1.0000x reference)
#include <cuda_runtime.h>
#include <cuda_fp16.h>
#include <cuda_bf16.h>
#include <cstdint>

#define N_NODES 50000
#define E_EDGES 800000
#define DIM     256
#define NHEAD   8
#define SCAN_BLK 1024
#define NBLK_SCAN ((N_NODES + SCAN_BLK - 1) / SCAN_BLK)   // 49

// ---------------- device scratch (allocation-free rule: use globals) -------
__device__ int    g_deg[N_NODES];          // zero-init at load; node_fused re-zeroes
__device__ __half g_xl_h[(size_t)N_NODES * DIM];   // x @ W_l (fp16)
__device__ __half g_xr_h[(size_t)N_NODES * DIM];   // x @ W_r (fp16)
__device__ int    g_row_start[N_NODES];
__device__ int    g_fill[N_NODES];
__device__ uint2  g_csr_rec[E_EDGES];              // {src, half2(ea0,ea1)} 8B
__device__ int    g_block_sums[64];
__device__ int    g_ctr1;                          // zero-init; reset each call
__device__ int    g_ctr2;
__device__ __half g_wl_ht[DIM * DIM];              // W_l^T in fp16 [n][k]
__device__ __half g_wr_ht[DIM * DIM];              // W_r^T in fp16 [n][k]

// ---------------- weight transpose-convert (both in one launch) -------------
__global__ void cvt_wt_both_kernel(const float* __restrict__ Wl,
                                   const float* __restrict__ Wr) {
    int i = blockIdx.x * blockDim.x + threadIdx.x;
    if (i >= 2 * DIM * DIM) return;
    int which = i >= DIM * DIM;
    int j = i - which * DIM * DIM;
    int n = j >> 8, k = j & 255;
    const float* W = which ? Wr : Wl;
    __half* Wt = which ? g_wr_ht : g_wl_ht;
    Wt[j] = __float2half_rn(W[k * DIM + n]);
}

// ---------------- degree count (g_deg pre-zeroed by previous call) ----------
__global__ void edge_stats_kernel(const int* __restrict__ edge_index) {
    int e = blockIdx.x * blockDim.x + threadIdx.x;
    if (e >= E_EDGES) return;
    atomicAdd(&g_deg[edge_index[E_EDGES + e]], 1);
}

// ---------------- fused exclusive scan (single kernel, 49 resident blocks) --
// Per-block scan, then counter-based grid sync (49 <= 148 SMs -> all resident,
// spin is deadlock-free), then each block adds sum of earlier block totals.
__global__ __launch_bounds__(SCAN_BLK)
void scan_fused_kernel() {
    __shared__ int warp_sums[32];
    int tid = threadIdx.x;
    int lane = tid & 31;
    int wid = tid >> 5;
    int bid = blockIdx.x;
    int idx = bid * SCAN_BLK + tid;

    int v = (idx < N_NODES) ? g_deg[idx] : 0;
    int incl = v;
#pragma unroll
    for (int off = 1; off < 32; off <<= 1) {
        int t = __shfl_up_sync(0xffffffffu, incl, off);
        if (lane >= off) incl += t;
    }
    if (lane == 31) warp_sums[wid] = incl;
    __syncthreads();
    if (wid == 0) {
        int w = warp_sums[lane];
        int wi = w;
#pragma unroll
        for (int off = 1; off < 32; off <<= 1) {
            int t = __shfl_up_sync(0xffffffffu, wi, off);
            if (lane >= off) wi += t;
        }
        warp_sums[lane] = wi - w;   // exclusive warp offsets
        if (lane == 31) {
            g_block_sums[bid] = wi;  // block total
            __threadfence();
            atomicAdd(&g_ctr1, 1);
        }
    }
    __syncthreads();   // FIX: warp0's exclusive offsets must be visible before read
    int local_excl = warp_sums[wid] + incl - v;

    // grid sync: wait until all block totals published
    __shared__ int s_boff;
    if (tid == 0) {
        while (atomicAdd(&g_ctr1, 0) < NBLK_SCAN) { }
    }
    __syncthreads();

    // own block offset = sum of block_sums[0..bid)
    if (wid == 0) {
        int a = (lane < bid && lane < NBLK_SCAN) ? g_block_sums[lane] : 0;
        int b = (lane + 32 < bid && lane + 32 < NBLK_SCAN) ? g_block_sums[lane + 32] : 0;
        int s = a + b;
#pragma unroll
        for (int off = 16; off > 0; off >>= 1)
            s += __shfl_xor_sync(0xffffffffu, s, off);
        if (lane == 0) s_boff = s;
    }
    __syncthreads();

    if (idx < N_NODES) {
        int rs = local_excl + s_boff;
        g_row_start[idx] = rs;
        g_fill[idx] = rs;
    }

    // reset counters for the next graph replay (block 0 waits for all)
    __syncthreads();
    if (tid == 0) {
        atomicAdd(&g_ctr2, 1);
        if (bid == 0) {
            while (atomicAdd(&g_ctr2, 0) < NBLK_SCAN) { }
            g_ctr1 = 0;
            g_ctr2 = 0;
            __threadfence();
        }
    }
}

// ---------------- CSR fill (packed 8B records, ea as half2) ------------------
__global__ void csr_fill_kernel(const int* __restrict__ edge_index,
                                const float* __restrict__ edge_attr) {
    int e = blockIdx.x * blockDim.x + threadIdx.x;
    if (e >= E_EDGES) return;
    int d = edge_index[E_EDGES + e];
    int pos = atomicAdd(&g_fill[d], 1);
    __half2 ea = __floats2half2_rn(edge_attr[2 * e], edge_attr[2 * e + 1]);
    uint2 r;
    r.x = (unsigned)edge_index[e];
    r.y = *(uint32_t*)&ea;
    g_csr_rec[pos] = r;
}

// ============================================================================
// FP16 tensor-core dual GEMM, fp32 A with fused fp16 convert in the loader.
// ============================================================================
#define GBM 128
#define GBN 128
#define GBK 32
#define PITCH 40

__device__ __forceinline__ void mma_f16(float4& d, const uint32_t* a, const uint32_t* b) {
    asm volatile(
        "mma.sync.aligned.m16n8k16.row.col.f32.f16.f16.f32 "
        "{%0,%1,%2,%3}, {%4,%5,%6,%7}, {%8,%9}, {%0,%1,%2,%3};"
        : "+f"(d.x), "+f"(d.y), "+f"(d.z), "+f"(d.w)
        : "r"(a[0]), "r"(a[1]), "r"(a[2]), "r"(a[3]), "r"(b[0]), "r"(b[1]));
}

__device__ __forceinline__ void ldsm_x4(uint32_t& r0, uint32_t& r1, uint32_t& r2, uint32_t& r3,
                                        uint32_t addr) {
    asm volatile("ldmatrix.sync.aligned.m8n8.x4.shared.b16 {%0,%1,%2,%3}, [%4];"
                 : "=r"(r0), "=r"(r1), "=r"(r2), "=r"(r3) : "r"(addr));
}

__device__ __forceinline__ void cp_async16(uint32_t smem_dst, const void* gmem_src, int src_bytes) {
    asm volatile("cp.async.cg.shared.global [%0], [%1], 16, %2;"
                 :: "r"(smem_dst), "l"(gmem_src), "r"(src_bytes));
}
__device__ __forceinline__ void cp_commit() { asm volatile("cp.async.commit_group;"); }
template<int NN> __device__ __forceinline__ void cp_wait() {
    asm volatile("cp.async.wait_group %0;" :: "n"(NN));
}

__device__ __forceinline__ uint32_t pack_h2(float a, float b) {
    __half2 h = __floats2half2_rn(a, b);
    return *(uint32_t*)&h;
}

__global__ __launch_bounds__(256, 2)
void gemm_f16_kernel(const float* __restrict__ A32,
                     int M) {
    __shared__ __half As[2][GBM * PITCH];
    __shared__ __half Bs[2][GBN * PITCH];

    const int tid  = threadIdx.x;
    const int wid  = tid >> 5;
    const int lane = tid & 31;
    const int g    = lane >> 2;
    const int tg   = lane & 3;

    const int warpM = wid & 1;
    const int warpN = wid >> 1;

    const int bm = blockIdx.x * GBM;
    const int bn = blockIdx.y * GBN;
    const __half* B = (blockIdx.z == 0) ? g_wl_ht : g_wr_ht;
    __half* Cout = (blockIdx.z == 0) ? g_xl_h : g_xr_h;

    const int rowA = (lane & 7) + 8 * ((lane >> 3) & 1);
    const int colA = (lane >> 4) * 8;
    const int qb   = lane >> 3;
    const int rowB = (lane & 7) + ((qb >> 1) * 8);
    const int colB = (qb & 1) * 8;

    uint32_t asBase[2], bsBase[2];
    asBase[0] = (uint32_t)__cvta_generic_to_shared(&As[0][0]);
    asBase[1] = (uint32_t)__cvta_generic_to_shared(&As[1][0]);
    bsBase[0] = (uint32_t)__cvta_generic_to_shared(&Bs[0][0]);
    bsBase[1] = (uint32_t)__cvta_generic_to_shared(&Bs[1][0]);

    float4 a_ld[4];
    auto loadA_regs = [&](int kt) {
#pragma unroll
        for (int r = 0; r < 4; r++) {
            int c = tid + r * 256;
            int row = c >> 3, c4 = c & 7;
            int grow = (bm + row < M) ? (bm + row) : bm;
            a_ld[r] = *(const float4*)&A32[(size_t)grow * DIM + kt + c4 * 4];
        }
    };
    auto storeA_smem = [&](int st) {
#pragma unroll
        for (int r = 0; r < 4; r++) {
            int c = tid + r * 256;
            int row = c >> 3, c4 = c & 7;
            uint2 h4 = make_uint2(pack_h2(a_ld[r].x, a_ld[r].y),
                                  pack_h2(a_ld[r].z, a_ld[r].w));
            *(uint2*)&As[st][row * PITCH + c4 * 4] = h4;
        }
    };
    auto loadB_tile = [&](int kt, int st) {
#pragma unroll
        for (int r = 0; r < 2; r++) {
            int f = tid + r * 256;
            int row = f >> 2, c = f & 3;
            const __half* srcB = &B[(size_t)(bn + row) * DIM + kt + c * 8];
            uint32_t dstB = (uint32_t)__cvta_generic_to_shared(&Bs[st][row * PITCH + c * 8]);
            cp_async16(dstB, srcB, 16);
        }
        cp_commit();
    };

    float4 acc[4][4];
#pragma unroll
    for (int i = 0; i < 4; i++)
#pragma unroll
        for (int j = 0; j < 4; j++) acc[i][j] = make_float4(0.f, 0.f, 0.f, 0.f);

    const int NITER = DIM / GBK;   // 8

    loadA_regs(0);
    loadB_tile(0, 0);
    storeA_smem(0);
    cp_wait<0>();
    __syncthreads();

    for (int it = 0; it < NITER; it++) {
        int st = it & 1;
        if (it + 1 < NITER) {
            loadA_regs((it + 1) * GBK);
            loadB_tile((it + 1) * GBK, st ^ 1);
        }

#pragma unroll
        for (int ks = 0; ks < 2; ks++) {
            int k0 = ks * 16;
            uint32_t af[4][4];
#pragma unroll
            for (int mt = 0; mt < 4; mt++) {
                int m0 = warpM * 64 + mt * 16;
                uint32_t addr = asBase[st] + 2u * ((m0 + rowA) * PITCH + k0 + colA);
                ldsm_x4(af[mt][0], af[mt][1], af[mt][2], af[mt][3], addr);
            }
            uint32_t bf[4][2];
#pragma unroll
            for (int ntp = 0; ntp < 2; ntp++) {
                int n0 = warpN * 32 + ntp * 16;
                uint32_t addr = bsBase[st] + 2u * ((n0 + rowB) * PITCH + k0 + colB);
                ldsm_x4(bf[2 * ntp][0], bf[2 * ntp][1], bf[2 * ntp + 1][0], bf[2 * ntp + 1][1], addr);
            }
#pragma unroll
            for (int mt = 0; mt < 4; mt++)
#pragma unroll
                for (int nt = 0; nt < 4; nt++)
                    mma_f16(acc[mt][nt], af[mt], bf[nt]);
        }

        if (it + 1 < NITER) {
            storeA_smem(st ^ 1);
            cp_wait<0>();
        }
        __syncthreads();
    }

#pragma unroll
    for (int mt = 0; mt < 4; mt++) {
        int r0 = bm + warpM * 64 + mt * 16 + g;
        int r1 = r0 + 8;
#pragma unroll
        for (int nt = 0; nt < 4; nt++) {
            int col = bn + warpN * 32 + nt * 8 + tg * 2;
            if (r0 < M)
                *(__half2*)&Cout[(size_t)r0 * DIM + col] = __floats2half2_rn(acc[mt][nt].x, acc[mt][nt].y);
            if (r1 < M)
                *(__half2*)&Cout[(size_t)r1 * DIM + col] = __floats2half2_rn(acc[mt][nt].z, acc[mt][nt].w);
        }
    }
}

// ============================================================================
// node-centric fused pass v7: warp per node, depth-1 prefetch, half2 score
// math; 8B CSR records (ea already half2). exp/denom/acc fp32. No atomics.
// ============================================================================
__global__ __launch_bounds__(256)
void node_fused_kernel(const float* __restrict__ W_e,
                       const float* __restrict__ att,
                       const float* __restrict__ bias,
                       float* __restrict__ out) {
    __shared__ float sWe0[DIM];
    __shared__ float sWe1[DIM];
    __shared__ float sAtt[DIM];
    __shared__ float sBias[DIM];
    for (int i = threadIdx.x; i < DIM; i += blockDim.x) {
        sWe0[i] = W_e[i];
        sWe1[i] = W_e[DIM + i];
        sAtt[i] = att[i] * 1.4426950408889634f;   // fold log2(e)
        sBias[i] = bias[i];
    }
    __syncthreads();

    int warp = (int)((blockIdx.x * (size_t)blockDim.x + threadIdx.x) >> 5);
    int lane = threadIdx.x & 31;
    if (warp >= N_NODES) return;
    int n = warp;
    int ch0 = lane * 8;

    __half2 xr2[4], we0h[4], we1h[4], avh[4];
    {
        uint4 rv = *(const uint4*)&g_xr_h[(size_t)n * DIM + ch0];
        const __half2* rh = (const __half2*)&rv;
#pragma unroll
        for (int q = 0; q < 4; q++) {
            xr2[q]  = rh[q];
            we0h[q] = __floats2half2_rn(sWe0[ch0 + 2 * q], sWe0[ch0 + 2 * q + 1]);
            we1h[q] = __floats2half2_rn(sWe1[ch0 + 2 * q], sWe1[ch0 + 2 * q + 1]);
            avh[q]  = __floats2half2_rn(sAtt[ch0 + 2 * q], sAtt[ch0 + 2 * q + 1]);
        }
    }
    const __half2 c02 = __float2half2_rn(0.2f);

    float acc[8] = {0.f, 0.f, 0.f, 0.f, 0.f, 0.f, 0.f, 0.f};
    float denom = 0.f;
    float eas0 = 0.f, eas1 = 0.f;

    int row = g_row_start[n];
    int deg = g_deg[n];

    auto do_edge = [&](__half2 eah, uint4 lv) {
        const __half2* lh = (const __half2*)&lv;
        __half2 e0h = __low2half2(eah);
        __half2 e1h = __high2half2(eah);
        __half2 p2 = __float2half2_rn(0.f);
        float xl[8];
#pragma unroll
        for (int q = 0; q < 4; q++) {
            __half2 m = __hadd2(lh[q], xr2[q]);
            m = __hfma2(e0h, we0h[q], m);
            m = __hfma2(e1h, we1h[q], m);
            m = __hmax2(m, __hmul2(m, c02));       // leaky relu
            p2 = __hfma2(m, avh[q], p2);
            float2 f = __half22float2(lh[q]);
            xl[2 * q] = f.x; xl[2 * q + 1] = f.y;
        }
        float2 pf = __half22float2(p2);
        float p = pf.x + pf.y;
        p += __shfl_xor_sync(0xffffffffu, p, 1);
        p += __shfl_xor_sync(0xffffffffu, p, 2);

        float ex = exp2f(p);
        denom += ex;
#pragma unroll
        for (int j = 0; j < 8; j++) acc[j] += ex * xl[j];
    };

    if (deg > 0) {
        uint2 rec = g_csr_rec[row];
        __half2 ea_cur = *(__half2*)&rec.y;
        uint4 lv_cur   = *(const uint4*)&g_xl_h[(size_t)rec.x * DIM + ch0];

        for (int i = 0; i < deg; i++) {
            __half2 ea_nxt = __float2half2_rn(0.f); uint4 lv_nxt;
            if (i + 1 < deg) {
                uint2 rn = g_csr_rec[row + i + 1];
                ea_nxt = *(__half2*)&rn.y;
                lv_nxt = *(const uint4*)&g_xl_h[(size_t)rn.x * DIM + ch0];
            }

            do_edge(ea_cur, lv_cur);
            {
                float2 f = __half22float2(ea_cur);
                eas0 += f.x; eas1 += f.y;
            }

            ea_cur = ea_nxt; lv_cur = lv_nxt;
        }
    }

    // self loop (loop_attr = mean incoming ea)
    {
        float invc = 1.0f / fmaxf((float)deg, 1.0f);
        uint4 lv = *(const uint4*)&g_xl_h[(size_t)n * DIM + ch0];
        do_edge(__floats2half2_rn(eas0 * invc, eas1 * invc), lv);
    }

    float inv = 1.0f / denom;
    float4 o0 = make_float4(acc[0] * inv + sBias[ch0 + 0], acc[1] * inv + sBias[ch0 + 1],
                            acc[2] * inv + sBias[ch0 + 2], acc[3] * inv + sBias[ch0 + 3]);
    float4 o1 = make_float4(acc[4] * inv + sBias[ch0 + 4], acc[5] * inv + sBias[ch0 + 5],
                            acc[6] * inv + sBias[ch0 + 6], acc[7] * inv + sBias[ch0 + 7]);
    *(float4*)&out[(size_t)n * DIM + ch0]     = o0;
    *(float4*)&out[(size_t)n * DIM + ch0 + 4] = o1;

    if (lane == 0) g_deg[n] = 0;   // reset for next replay
}

// ---------------- launch: fork GEMM branch onto a side stream ---------------
extern "C" void kernel_launch(void* const* d_in, const int* in_sizes, int n_in,
                              void* d_out, int out_size) {
    const float* x          = (const float*)d_in[0];
    const int*   edge_index = (const int*)  d_in[1];
    const float* edge_attr  = (const float*)d_in[2];
    const float* W_l        = (const float*)d_in[3];
    const float* W_r        = (const float*)d_in[4];
    const float* W_e        = (const float*)d_in[5];
    const float* att        = (const float*)d_in[6];
    const float* bias       = (const float*)d_in[7];
    float* out = (float*)d_out;

    cudaStream_t s1;
    cudaStreamCreateWithFlags(&s1, cudaStreamNonBlocking);
    cudaEvent_t ev_fork, ev_gemm;
    cudaEventCreateWithFlags(&ev_fork, cudaEventDisableTiming);
    cudaEventCreateWithFlags(&ev_gemm, cudaEventDisableTiming);

    // fork
    cudaEventRecord(ev_fork, 0);
    cudaStreamWaitEvent(s1, ev_fork, 0);

    // branch A (side stream): weight convert + dual GEMM (x converted in-loader)
    cvt_wt_both_kernel<<<(2 * DIM * DIM + 255) / 256, 256, 0, s1>>>(W_l, W_r);
    dim3 ggrid((N_NODES + GBM - 1) / GBM, DIM / GBN, 2);
    gemm_f16_kernel<<<ggrid, 256, 0, s1>>>(x, N_NODES);
    cudaEventRecord(ev_gemm, s1);

    // branch B (capture stream): CSR build (g_deg pre-zeroed by prior call)
    edge_stats_kernel<<<(E_EDGES + 511) / 512, 512>>>(edge_index);
    scan_fused_kernel<<<NBLK_SCAN, SCAN_BLK>>>();
    csr_fill_kernel<<<(E_EDGES + 255) / 256, 256>>>(edge_index, edge_attr);

    // join
    cudaStreamWaitEvent(0, ev_gemm, 0);

    int nblk = (N_NODES + 7) / 8;   // 8 warps per block
    node_fused_kernel<<<nblk, 256>>>(W_e, att, bias, out);
}